// round 1
// baseline (speedup 1.0000x reference)
#include <cuda_runtime.h>
#include <cstdint>
#include <cstddef>

// Problem constants
#define HH   32
#define NQ   2048
#define TT   2048
#define DD   128
#define RRNK 64
#define KAUG 192   // 128 (quant key / q) + 64 (sign / proj)

// Scratch: augmented operands, tf32-rounded fp32.
// A'[h][n][0:128] = tf32(q), A'[h][n][128+r] = tf32((q@G)_r / 64)
// B'[h][t][0:128] = tf32(k_quant), B'[h][t][128+r] = sign((k_orig-k_quant)@G)_r
__device__ __align__(16) float g_Aaug[(size_t)HH * NQ * KAUG];
__device__ __align__(16) float g_Baug[(size_t)HH * TT * KAUG];

__device__ __forceinline__ float to_tf32(float x) {
    unsigned u;
    asm("cvt.rna.tf32.f32 %0, %1;" : "=r"(u) : "f"(x));
    return __uint_as_float(u);
}

__device__ __forceinline__ float sgnf(float x) {
    return (x > 0.0f) ? 1.0f : ((x < 0.0f) ? -1.0f : 0.0f);
}

// ---------------------------------------------------------------------------
// Prep kernel: 4096 blocks x 128 threads.
//   blocks [0,2048)    : build A' (from q)
//   blocks [2048,4096) : build B' (from k_orig, k_quant)
// Each block handles 32 rows of one tensor. Phase 1 stages the 128-dim vector
// (q or residual e) transposed in smem and writes the tf32 "head" part of the
// augmented row. Phase 2 does a register-blocked 4x4 (rows x r) projection
// against G with float4 loads, then writes the 64-wide "tail".
// ---------------------------------------------------------------------------
__global__ void prep_kernel(const float* __restrict__ q,
                            const float* __restrict__ ko,
                            const float* __restrict__ kq,
                            const float* __restrict__ G) {
    __shared__ float et[128][36];   // [d][row], padded for bank-conflict-free f4

    const int tid  = threadIdx.x;            // 0..127
    const int mode = blockIdx.x >> 11;       // 0 = A-side, 1 = B-side
    const int blk  = blockIdx.x & 2047;
    const int row0 = blk * 32;                // global row index over H*2048

    // ---- Phase 1: stage vectors, emit tf32 head part ----
    if (mode == 0) {
        #pragma unroll 4
        for (int rr = 0; rr < 32; rr++) {
            const int row = row0 + rr;
            const float v = q[(size_t)row * DD + tid];
            et[tid][rr] = v;
            g_Aaug[(size_t)row * KAUG + tid] = to_tf32(v);
        }
    } else {
        #pragma unroll 4
        for (int rr = 0; rr < 32; rr++) {
            const int row = row0 + rr;
            const float a = ko[(size_t)row * DD + tid];
            const float b = kq[(size_t)row * DD + tid];
            et[tid][rr] = a - b;                       // residual e
            g_Baug[(size_t)row * KAUG + tid] = to_tf32(b);
        }
    }
    __syncthreads();

    // ---- Phase 2: 4 rows x 4 r per thread ----
    const int rowblk = tid >> 4;        // 0..7 -> rows rowblk*4 .. +3
    const int r0     = (tid & 15) * 4;  // 0..60

    float acc[4][4];
    #pragma unroll
    for (int i = 0; i < 4; i++)
        #pragma unroll
        for (int j = 0; j < 4; j++) acc[i][j] = 0.0f;

    #pragma unroll 4
    for (int d = 0; d < 128; d++) {
        const float4 ev = *(const float4*)&et[d][rowblk * 4];
        const float4 gv = *(const float4*)(G + d * RRNK + r0);
        const float e0 = ev.x, e1 = ev.y, e2 = ev.z, e3 = ev.w;
        const float g0 = gv.x, g1 = gv.y, g2 = gv.z, g3 = gv.w;
        acc[0][0] += e0 * g0; acc[0][1] += e0 * g1; acc[0][2] += e0 * g2; acc[0][3] += e0 * g3;
        acc[1][0] += e1 * g0; acc[1][1] += e1 * g1; acc[1][2] += e1 * g2; acc[1][3] += e1 * g3;
        acc[2][0] += e2 * g0; acc[2][1] += e2 * g1; acc[2][2] += e2 * g2; acc[2][3] += e2 * g3;
        acc[3][0] += e3 * g0; acc[3][1] += e3 * g1; acc[3][2] += e3 * g2; acc[3][3] += e3 * g3;
    }

    #pragma unroll
    for (int i = 0; i < 4; i++) {
        const int row = row0 + rowblk * 4 + i;
        float4 o;
        if (mode == 0) {
            const float sc = 1.0f / 64.0f;   // (1/sqrt(R)) * alpha = 1/64
            o.x = to_tf32(acc[i][0] * sc);
            o.y = to_tf32(acc[i][1] * sc);
            o.z = to_tf32(acc[i][2] * sc);
            o.w = to_tf32(acc[i][3] * sc);
            *(float4*)&g_Aaug[(size_t)row * KAUG + DD + r0] = o;
        } else {
            o.x = sgnf(acc[i][0]);
            o.y = sgnf(acc[i][1]);
            o.z = sgnf(acc[i][2]);
            o.w = sgnf(acc[i][3]);
            *(float4*)&g_Baug[(size_t)row * KAUG + DD + r0] = o;
        }
    }
}

// ---------------------------------------------------------------------------
// Main GEMM: out[h] = A'[h] (2048x192) * B'[h]^T (192x2048), fp32 out.
// Grid (16 ntile, 16 mtile, 32 head), 256 threads (8 warps).
// CTA tile 128x128, full K=192 resident in smem (padded rows of 196 floats).
// Warp tile 64x32 via mma.sync.m16n8k8 tf32 (4x4 mma fragments per k8 step).
// ---------------------------------------------------------------------------
#define SMEM_ROW 196
#define GEMM_SMEM_BYTES (2 * 128 * SMEM_ROW * 4)

__global__ __launch_bounds__(256, 1)
void gemm_kernel(float* __restrict__ out) {
    extern __shared__ float sm[];
    float* As = sm;                       // [128][196]
    float* Bs = sm + 128 * SMEM_ROW;      // [128][196]

    const int h  = blockIdx.z;
    const int mt = blockIdx.y;
    const int nt = blockIdx.x;

    const float* Ag = g_Aaug + ((size_t)h * NQ + (size_t)mt * 128) * KAUG;
    const float* Bg = g_Baug + ((size_t)h * TT + (size_t)nt * 128) * KAUG;

    const int tid = threadIdx.x;

    // Load both 128x192 tiles (float4, fully coalesced)
    #pragma unroll 4
    for (int i = tid; i < 128 * 48; i += 256) {
        const int row = i / 48;
        const int c4  = (i % 48) * 4;
        *(float4*)(As + row * SMEM_ROW + c4) = *(const float4*)(Ag + row * KAUG + c4);
        *(float4*)(Bs + row * SMEM_ROW + c4) = *(const float4*)(Bg + row * KAUG + c4);
    }
    __syncthreads();

    const int wid  = tid >> 5;
    const int lane = tid & 31;
    const int wm   = wid >> 2;      // 0..1 -> 64-row band
    const int wn   = wid & 3;       // 0..3 -> 32-col band
    const int g    = lane >> 2;     // groupID 0..7
    const int t4   = lane & 3;      // 0..3

    float c[4][4][4];               // [im][in][4 accum regs]
    #pragma unroll
    for (int im = 0; im < 4; im++)
        #pragma unroll
        for (int jn = 0; jn < 4; jn++)
            #pragma unroll
            for (int k = 0; k < 4; k++) c[im][jn][k] = 0.0f;

    #pragma unroll 2
    for (int k0 = 0; k0 < KAUG; k0 += 8) {
        unsigned a[4][4], b[4][2];
        #pragma unroll
        for (int im = 0; im < 4; im++) {
            const int m = wm * 64 + im * 16 + g;
            const float* p0 = As + m * SMEM_ROW + k0 + t4;
            const float* p1 = As + (m + 8) * SMEM_ROW + k0 + t4;
            a[im][0] = __float_as_uint(p0[0]);
            a[im][1] = __float_as_uint(p1[0]);
            a[im][2] = __float_as_uint(p0[4]);
            a[im][3] = __float_as_uint(p1[4]);
        }
        #pragma unroll
        for (int jn = 0; jn < 4; jn++) {
            const int n = wn * 32 + jn * 8 + g;
            const float* pb = Bs + n * SMEM_ROW + k0 + t4;
            b[jn][0] = __float_as_uint(pb[0]);
            b[jn][1] = __float_as_uint(pb[4]);
        }
        #pragma unroll
        for (int im = 0; im < 4; im++) {
            #pragma unroll
            for (int jn = 0; jn < 4; jn++) {
                asm volatile(
                    "mma.sync.aligned.m16n8k8.row.col.f32.tf32.tf32.f32 "
                    "{%0,%1,%2,%3}, {%4,%5,%6,%7}, {%8,%9}, {%0,%1,%2,%3};"
                    : "+f"(c[im][jn][0]), "+f"(c[im][jn][1]),
                      "+f"(c[im][jn][2]), "+f"(c[im][jn][3])
                    : "r"(a[im][0]), "r"(a[im][1]), "r"(a[im][2]), "r"(a[im][3]),
                      "r"(b[jn][0]), "r"(b[jn][1]));
            }
        }
    }

    // Epilogue: float2 stores
    float* C = out + ((size_t)h * NQ + (size_t)mt * 128) * (size_t)TT + (size_t)nt * 128;
    #pragma unroll
    for (int im = 0; im < 4; im++) {
        const int row = wm * 64 + im * 16 + g;
        #pragma unroll
        for (int jn = 0; jn < 4; jn++) {
            const int col = wn * 32 + jn * 8 + 2 * t4;
            float2 v0; v0.x = c[im][jn][0]; v0.y = c[im][jn][1];
            float2 v1; v1.x = c[im][jn][2]; v1.y = c[im][jn][3];
            *(float2*)(C + (size_t)row * TT + col)       = v0;
            *(float2*)(C + (size_t)(row + 8) * TT + col) = v1;
        }
    }
}

// ---------------------------------------------------------------------------
extern "C" void kernel_launch(void* const* d_in, const int* in_sizes, int n_in,
                              void* d_out, int out_size) {
    const float* q  = (const float*)d_in[0];   // (1,32,2048,128)
    const float* ko = (const float*)d_in[1];   // (1,32,2048,128)
    const float* kq = (const float*)d_in[2];   // (1,32,2048,128)
    const float* G  = (const float*)d_in[3];   // (128,64)
    float* out = (float*)d_out;                // (1,32,2048,2048)

    prep_kernel<<<4096, 128>>>(q, ko, kq, G);

    cudaFuncSetAttribute(gemm_kernel,
                         cudaFuncAttributeMaxDynamicSharedMemorySize,
                         GEMM_SMEM_BYTES);
    dim3 grid(TT / 128, NQ / 128, HH);
    gemm_kernel<<<grid, 256, GEMM_SMEM_BYTES>>>(out);
}

// round 2
// speedup vs baseline: 1.4070x; 1.4070x over previous
#include <cuda_runtime.h>
#include <cstdint>
#include <cstddef>

// Problem constants
#define HH   32
#define NQ   2048
#define TT   2048
#define DD   128
#define RRNK 64
#define KAUG 192   // 128 (quant key / q) + 64 (sign / proj)

// Scratch: augmented tf32-rounded operands.
// A'[h][n][0:128]=tf32(q),      A'[h][n][128+r]=tf32((q@G)_r/64)
// B'[h][t][0:128]=tf32(k_quant), B'[h][t][128+r]=sign((k_orig-k_quant)@G)_r
__device__ __align__(16) float g_Aaug[(size_t)HH * NQ * KAUG];
__device__ __align__(16) float g_Baug[(size_t)HH * TT * KAUG];

__device__ __forceinline__ float to_tf32(float x) {
    unsigned u;
    asm("cvt.rna.tf32.f32 %0, %1;" : "=r"(u) : "f"(x));
    return __uint_as_float(u);
}
__device__ __forceinline__ float sgnf(float x) {
    return (x > 0.0f) ? 1.0f : ((x < 0.0f) ? -1.0f : 0.0f);
}

// ---------------------------------------------------------------------------
// Prep (tensor-core version): grid (16 mtiles, 32 heads, 2 modes), 256 thr.
// Stages 128 rows of q (or residual e) + G^T in smem, runs the 128x64x128
// JL projection on mma.m16n8k8.tf32, writes the augmented head+tail rows.
// ---------------------------------------------------------------------------
#define PREP_SMEM_BYTES ((128 * 132 + 64 * 132) * 4)

__global__ __launch_bounds__(256)
void prep_mma_kernel(const float* __restrict__ q,
                     const float* __restrict__ ko,
                     const float* __restrict__ kq,
                     const float* __restrict__ G) {
    extern __shared__ float psm[];
    float* Vs = psm;              // [128][132] staged vectors (tf32)
    float* Gs = psm + 128 * 132;  // [64][132]  G transposed   (tf32)

    const int tid  = threadIdx.x;
    const int mt   = blockIdx.x;
    const int h    = blockIdx.y;
    const int mode = blockIdx.z;              // 0 = A-side(q), 1 = B-side(keys)
    const size_t row0 = (size_t)h * 2048 + (size_t)mt * 128;

    // Stage G transposed: Gs[r][d] = tf32(G[d][r])
    for (int idx = tid; idx < 128 * 64; idx += 256) {
        const int d = idx >> 6, r = idx & 63;
        Gs[r * 132 + d] = to_tf32(G[idx]);
    }
    // Stage vectors + emit head part of augmented rows
    if (mode == 0) {
        for (int idx = tid; idx < 128 * 128; idx += 256) {
            const int r = idx >> 7, d = idx & 127;
            const float tv = to_tf32(q[(row0 + r) * DD + d]);
            Vs[r * 132 + d] = tv;
            g_Aaug[(row0 + r) * KAUG + d] = tv;
        }
    } else {
        for (int idx = tid; idx < 128 * 128; idx += 256) {
            const int r = idx >> 7, d = idx & 127;
            const size_t gi = (row0 + r) * DD + d;
            const float a = ko[gi], b = kq[gi];
            Vs[r * 132 + d] = to_tf32(a - b);          // residual e
            g_Baug[(row0 + r) * KAUG + d] = to_tf32(b);
        }
    }
    __syncthreads();

    const int wid = tid >> 5, lane = tid & 31;
    const int g = lane >> 2, t4 = lane & 3;

    float c[8][4];
    #pragma unroll
    for (int j = 0; j < 8; j++)
        #pragma unroll
        for (int k = 0; k < 4; k++) c[j][k] = 0.0f;

    #pragma unroll 2
    for (int k0 = 0; k0 < 128; k0 += 8) {
        unsigned a[4];
        const float* p0 = Vs + (wid * 16 + g) * 132 + k0 + t4;
        const float* p1 = p0 + 8 * 132;
        a[0] = __float_as_uint(p0[0]);
        a[1] = __float_as_uint(p1[0]);
        a[2] = __float_as_uint(p0[4]);
        a[3] = __float_as_uint(p1[4]);
        #pragma unroll
        for (int jn = 0; jn < 8; jn++) {
            const float* pb = Gs + (jn * 8 + g) * 132 + k0 + t4;
            const unsigned b0 = __float_as_uint(pb[0]);
            const unsigned b1 = __float_as_uint(pb[4]);
            asm volatile(
                "mma.sync.aligned.m16n8k8.row.col.f32.tf32.tf32.f32 "
                "{%0,%1,%2,%3}, {%4,%5,%6,%7}, {%8,%9}, {%0,%1,%2,%3};"
                : "+f"(c[jn][0]), "+f"(c[jn][1]), "+f"(c[jn][2]), "+f"(c[jn][3])
                : "r"(a[0]), "r"(a[1]), "r"(a[2]), "r"(a[3]),
                  "r"(b0), "r"(b1));
        }
    }

    // Tail epilogue
    const size_t rg = row0 + wid * 16 + g;
    #pragma unroll
    for (int jn = 0; jn < 8; jn++) {
        const int col = 128 + jn * 8 + 2 * t4;
        if (mode == 0) {
            const float sc = 1.0f / 64.0f;   // (1/sqrt(R)) * alpha
            float2 v0, v1;
            v0.x = to_tf32(c[jn][0] * sc); v0.y = to_tf32(c[jn][1] * sc);
            v1.x = to_tf32(c[jn][2] * sc); v1.y = to_tf32(c[jn][3] * sc);
            *(float2*)&g_Aaug[rg * KAUG + col]       = v0;
            *(float2*)&g_Aaug[(rg + 8) * KAUG + col] = v1;
        } else {
            float2 v0, v1;
            v0.x = sgnf(c[jn][0]); v0.y = sgnf(c[jn][1]);
            v1.x = sgnf(c[jn][2]); v1.y = sgnf(c[jn][3]);
            *(float2*)&g_Baug[rg * KAUG + col]       = v0;
            *(float2*)&g_Baug[(rg + 8) * KAUG + col] = v1;
        }
    }
}

// ---------------------------------------------------------------------------
// Main GEMM: out[h] = A'[h](2048x192) * B'[h]^T, fp32.
// CTA tile 128x128; K split into 6 chunks of 32 floats, cp.async
// double-buffered (64+ KB smem -> 2 CTAs/SM). Warp tile 64x32 tf32 mma.
// ---------------------------------------------------------------------------
#define KC     32
#define ROWP   36
#define BUFSZ  (128 * ROWP)                 // floats, one tensor one buffer
#define GEMM_SMEM_BYTES (4 * BUFSZ * 4)     // 73728 bytes

__global__ __launch_bounds__(256, 2)
void gemm_kernel(float* __restrict__ out) {
    extern __shared__ float sm[];
    // As buf b: sm + b*BUFSZ ; Bs buf b: sm + 2*BUFSZ + b*BUFSZ

    const int h  = blockIdx.z;
    const int mt = blockIdx.y;
    const int nt = blockIdx.x;
    const float* Ag = g_Aaug + ((size_t)h * NQ + (size_t)mt * 128) * KAUG;
    const float* Bg = g_Baug + ((size_t)h * TT + (size_t)nt * 128) * KAUG;

    const int tid = threadIdx.x;

    auto prefetch = [&](int chunk, int buf) {
        #pragma unroll
        for (int i = 0; i < 8; i++) {
            const int id   = i * 256 + tid;
            const int bsel = id >> 10;          // 0 = A, 1 = B
            const int rid  = id & 1023;
            const int row  = rid >> 3;
            const int c0   = (rid & 7) * 4;     // float offset within chunk
            float* dst = sm + bsel * 2 * BUFSZ + buf * BUFSZ + row * ROWP + c0;
            const float* src = (bsel ? Bg : Ag) + (size_t)row * KAUG + chunk * KC + c0;
            const unsigned sdst = (unsigned)__cvta_generic_to_shared(dst);
            asm volatile("cp.async.cg.shared.global [%0], [%1], 16;"
                         :: "r"(sdst), "l"(src));
        }
    };

    const int wid  = tid >> 5;
    const int lane = tid & 31;
    const int wm   = wid >> 2;      // 0..1
    const int wn   = wid & 3;       // 0..3
    const int g    = lane >> 2;
    const int t4   = lane & 3;

    float c[4][4][4];
    #pragma unroll
    for (int im = 0; im < 4; im++)
        #pragma unroll
        for (int jn = 0; jn < 4; jn++)
            #pragma unroll
            for (int k = 0; k < 4; k++) c[im][jn][k] = 0.0f;

    prefetch(0, 0);
    asm volatile("cp.async.commit_group;");

    for (int ch = 0; ch < 6; ch++) {
        if (ch < 5) {
            prefetch(ch + 1, (ch + 1) & 1);
            asm volatile("cp.async.commit_group;");
            asm volatile("cp.async.wait_group 1;");
        } else {
            asm volatile("cp.async.wait_group 0;");
        }
        __syncthreads();

        const float* As = sm + (ch & 1) * BUFSZ;
        const float* Bs = sm + 2 * BUFSZ + (ch & 1) * BUFSZ;

        #pragma unroll
        for (int ks = 0; ks < 4; ks++) {
            const int k0 = ks * 8;
            unsigned a[4][4], b[4][2];
            #pragma unroll
            for (int im = 0; im < 4; im++) {
                const int m = wm * 64 + im * 16 + g;
                const float* p0 = As + m * ROWP + k0 + t4;
                const float* p1 = As + (m + 8) * ROWP + k0 + t4;
                a[im][0] = __float_as_uint(p0[0]);
                a[im][1] = __float_as_uint(p1[0]);
                a[im][2] = __float_as_uint(p0[4]);
                a[im][3] = __float_as_uint(p1[4]);
            }
            #pragma unroll
            for (int jn = 0; jn < 4; jn++) {
                const int n = wn * 32 + jn * 8 + g;
                const float* pb = Bs + n * ROWP + k0 + t4;
                b[jn][0] = __float_as_uint(pb[0]);
                b[jn][1] = __float_as_uint(pb[4]);
            }
            #pragma unroll
            for (int im = 0; im < 4; im++) {
                #pragma unroll
                for (int jn = 0; jn < 4; jn++) {
                    asm volatile(
                        "mma.sync.aligned.m16n8k8.row.col.f32.tf32.tf32.f32 "
                        "{%0,%1,%2,%3}, {%4,%5,%6,%7}, {%8,%9}, {%0,%1,%2,%3};"
                        : "+f"(c[im][jn][0]), "+f"(c[im][jn][1]),
                          "+f"(c[im][jn][2]), "+f"(c[im][jn][3])
                        : "r"(a[im][0]), "r"(a[im][1]), "r"(a[im][2]), "r"(a[im][3]),
                          "r"(b[jn][0]), "r"(b[jn][1]));
                }
            }
        }
        __syncthreads();
    }

    // Epilogue
    float* C = out + ((size_t)h * NQ + (size_t)mt * 128) * (size_t)TT + (size_t)nt * 128;
    #pragma unroll
    for (int im = 0; im < 4; im++) {
        const int row = wm * 64 + im * 16 + g;
        #pragma unroll
        for (int jn = 0; jn < 4; jn++) {
            const int col = wn * 32 + jn * 8 + 2 * t4;
            float2 v0; v0.x = c[im][jn][0]; v0.y = c[im][jn][1];
            float2 v1; v1.x = c[im][jn][2]; v1.y = c[im][jn][3];
            *(float2*)(C + (size_t)row * TT + col)       = v0;
            *(float2*)(C + (size_t)(row + 8) * TT + col) = v1;
        }
    }
}

// ---------------------------------------------------------------------------
extern "C" void kernel_launch(void* const* d_in, const int* in_sizes, int n_in,
                              void* d_out, int out_size) {
    const float* q  = (const float*)d_in[0];   // (1,32,2048,128)
    const float* ko = (const float*)d_in[1];   // (1,32,2048,128)
    const float* kq = (const float*)d_in[2];   // (1,32,2048,128)
    const float* G  = (const float*)d_in[3];   // (128,64)
    float* out = (float*)d_out;                // (1,32,2048,2048)

    cudaFuncSetAttribute(prep_mma_kernel,
                         cudaFuncAttributeMaxDynamicSharedMemorySize,
                         PREP_SMEM_BYTES);
    dim3 pgrid(16, 32, 2);
    prep_mma_kernel<<<pgrid, 256, PREP_SMEM_BYTES>>>(q, ko, kq, G);

    cudaFuncSetAttribute(gemm_kernel,
                         cudaFuncAttributeMaxDynamicSharedMemorySize,
                         GEMM_SMEM_BYTES);
    dim3 grid(TT / 128, NQ / 128, HH);
    gemm_kernel<<<grid, 256, GEMM_SMEM_BYTES>>>(out);
}